// round 15
// baseline (speedup 1.0000x reference)
#include <cuda_runtime.h>
#include <cuda_fp16.h>
#include <cstdint>

#define BATCH 4
#define SEQ   2048
#define DMODEL 1024
#define NHEAD 16
#define DK    64
#define SCALE 0.125f

// ---------------- scratch (device globals; no allocation allowed) ----------------
__device__ __half g_Xh[3][(size_t)BATCH * SEQ * DMODEL];     // fp16 inputs
__device__ __half g_Wh[4][(size_t)DMODEL * DMODEL];          // fp16 weights (q,k,v,o)
__device__ __half g_Qh[(size_t)BATCH * NHEAD * SEQ * DK];    // [b,h,s,dk]
__device__ __half g_Kh[(size_t)BATCH * NHEAD * SEQ * DK];    // [b,h,s,dk]
__device__ __half g_Vt[(size_t)BATCH * NHEAD * DK * SEQ];    // [b,h,dk,s]  (transposed)
__device__ __half g_P [(size_t)BATCH * NHEAD * SEQ * SEQ];   // 512 MB unnormalized probs
__device__ __half g_Ch[(size_t)BATCH * SEQ * DMODEL];        // context fp16 [B,S,D]
__device__ float  g_rowsum[(size_t)BATCH * NHEAD * SEQ];

// =====================================================================
// single fused fp32->fp16 conversion over all 7 tensors
// =====================================================================
#define NX4 (BATCH * SEQ * DMODEL / 4)     // 2097152
#define NW4 (DMODEL * DMODEL / 4)          // 262144
__global__ __launch_bounds__(256) void cvt_all(
    const float* __restrict__ q, const float* __restrict__ k, const float* __restrict__ v,
    const float* __restrict__ wq, const float* __restrict__ wk,
    const float* __restrict__ wv, const float* __restrict__ wo) {
    int i = blockIdx.x * 256 + threadIdx.x;
    const float* src; __half* dst; int off;
    if (i < 3 * NX4) {
        int w = i / NX4; off = i - w * NX4;
        src = (w == 0) ? q : (w == 1) ? k : v;
        dst = g_Xh[w];
    } else {
        int j = i - 3 * NX4;
        int w = j / NW4; off = j - w * NW4;
        src = (w == 0) ? wq : (w == 1) ? wk : (w == 2) ? wv : wo;
        dst = g_Wh[w];
    }
    float4 val = ((const float4*)src)[off];
    __half2* dp = (__half2*)dst + off * 2;
    dp[0] = __floats2half2_rn(val.x, val.y);
    dp[1] = __floats2half2_rn(val.z, val.w);
}

// ---------------- mma / async helpers ----------------
__device__ __forceinline__ uint32_t smaddr(const void* p) {
    return (uint32_t)__cvta_generic_to_shared(p);
}
__device__ __forceinline__ void ldsm4(uint32_t& a0, uint32_t& a1, uint32_t& a2, uint32_t& a3,
                                      uint32_t addr) {
    asm volatile("ldmatrix.sync.aligned.m8n8.x4.shared.b16 {%0,%1,%2,%3}, [%4];\n"
                 : "=r"(a0), "=r"(a1), "=r"(a2), "=r"(a3) : "r"(addr));
}
__device__ __forceinline__ void ldsm2(uint32_t& b0, uint32_t& b1, uint32_t addr) {
    asm volatile("ldmatrix.sync.aligned.m8n8.x2.shared.b16 {%0,%1}, [%2];\n"
                 : "=r"(b0), "=r"(b1) : "r"(addr));
}
__device__ __forceinline__ void mma16816(float* c, uint32_t a0, uint32_t a1, uint32_t a2,
                                         uint32_t a3, uint32_t b0, uint32_t b1) {
    asm volatile("mma.sync.aligned.m16n8k16.row.col.f32.f16.f16.f32 "
                 "{%0,%1,%2,%3}, {%4,%5,%6,%7}, {%8,%9}, {%0,%1,%2,%3};\n"
                 : "+f"(c[0]), "+f"(c[1]), "+f"(c[2]), "+f"(c[3])
                 : "r"(a0), "r"(a1), "r"(a2), "r"(a3), "r"(b0), "r"(b1));
}
__device__ __forceinline__ void cp_async16(uint32_t s, const void* g) {
    asm volatile("cp.async.cg.shared.global [%0], [%1], 16;\n" :: "r"(s), "l"(g));
}
#define CP_COMMIT() asm volatile("cp.async.commit_group;\n" ::: "memory")
#define CP_WAIT0()  asm volatile("cp.async.wait_group 0;\n" ::: "memory")

#define LDS 40   // padded leading dim (halfs): conflict-free ldmatrix

// =====================================================================
// 128x128 HMMA GEMM, 2-stage cp.async pipeline, k-tile 32.
// EPI 0: QKV proj (z=which; V written transposed).  EPI 2: out-proj + bias.
// =====================================================================
template<int EPI>
__global__ __launch_bounds__(256) void mgemm(const float* __restrict__ bias,
                                             float* __restrict__ Cp) {
    __shared__ __align__(16) __half As[2][128 * LDS];
    __shared__ __align__(16) __half Bs[2][128 * LDS];

    const int z = blockIdx.z;
    const __half* A; const __half* B;
    if constexpr (EPI == 0) { A = g_Xh[z]; B = g_Wh[z]; }
    else { A = g_Ch; B = g_Wh[3]; }
    const int lda = DMODEL;
    const int ktiles = DMODEL / 32;

    const int tid = threadIdx.x;
    const int m0 = blockIdx.y * 128, n0 = blockIdx.x * 128;
    const int wid = tid >> 5, lane = tid & 31;
    const int wy = wid >> 2, wx = wid & 3;

    // loader: 2 chunks (16B) per thread per matrix per stage
    const int ch0 = tid * 2, ch1 = tid * 2 + 1;
    const int c0r = ch0 >> 2, c0c = (ch0 & 3) * 8;
    const int c1r = ch1 >> 2, c1c = (ch1 & 3) * 8;

    const __half* Arow0 = A + (size_t)(m0 + c0r) * lda + c0c;
    const __half* Arow1 = A + (size_t)(m0 + c1r) * lda + c1c;
    const __half* Brow0 = B + (size_t)(n0 + c0r) * lda + c0c;
    const __half* Brow1 = B + (size_t)(n0 + c1r) * lda + c1c;

    // prologue: stage 0
    {
        cp_async16(smaddr(&As[0][c0r * LDS + c0c]), Arow0);
        cp_async16(smaddr(&As[0][c1r * LDS + c1c]), Arow1);
        cp_async16(smaddr(&Bs[0][c0r * LDS + c0c]), Brow0);
        cp_async16(smaddr(&Bs[0][c1r * LDS + c1c]), Brow1);
        CP_COMMIT();
    }

    int aoff[4], boff[4];
#pragma unroll
    for (int mt = 0; mt < 4; mt++)
        aoff[mt] = (wy * 64 + mt * 16 + (lane & 15)) * LDS + (lane >> 4) * 8;
#pragma unroll
    for (int nt = 0; nt < 4; nt++)
        boff[nt] = (wx * 32 + nt * 8 + (lane & 7)) * LDS + ((lane >> 3) & 1) * 8;

    float acc[4][4][4];
#pragma unroll
    for (int i = 0; i < 4; i++)
#pragma unroll
        for (int j = 0; j < 4; j++)
#pragma unroll
            for (int k = 0; k < 4; k++) acc[i][j][k] = 0.f;

#pragma unroll 1
    for (int t = 0; t < ktiles; t++) {
        CP_WAIT0();
        __syncthreads();

        if (t + 1 < ktiles) {
            const int nx = (t + 1) & 1;
            const int ko = (t + 1) * 32;
            cp_async16(smaddr(&As[nx][c0r * LDS + c0c]), Arow0 + ko);
            cp_async16(smaddr(&As[nx][c1r * LDS + c1c]), Arow1 + ko);
            cp_async16(smaddr(&Bs[nx][c0r * LDS + c0c]), Brow0 + ko);
            cp_async16(smaddr(&Bs[nx][c1r * LDS + c1c]), Brow1 + ko);
            CP_COMMIT();
        }

        const int cur = t & 1;
#pragma unroll
        for (int ks = 0; ks < 2; ks++) {
            uint32_t af[4][4], bf[4][2];
#pragma unroll
            for (int mt = 0; mt < 4; mt++)
                ldsm4(af[mt][0], af[mt][1], af[mt][2], af[mt][3],
                      smaddr(&As[cur][aoff[mt] + ks * 16]));
#pragma unroll
            for (int nt = 0; nt < 4; nt++)
                ldsm2(bf[nt][0], bf[nt][1], smaddr(&Bs[cur][boff[nt] + ks * 16]));
#pragma unroll
            for (int mt = 0; mt < 4; mt++)
#pragma unroll
                for (int nt = 0; nt < 4; nt++)
                    mma16816(acc[mt][nt], af[mt][0], af[mt][1], af[mt][2], af[mt][3],
                             bf[nt][0], bf[nt][1]);
        }
        __syncthreads();
    }

    if constexpr (EPI == 0) {
#pragma unroll
        for (int mt = 0; mt < 4; mt++) {
            int rA = m0 + wy * 64 + mt * 16 + (lane >> 2);
#pragma unroll
            for (int half_ = 0; half_ < 2; half_++) {
                int r = rA + half_ * 8;
                int b = r >> 11, s = r & (SEQ - 1);
#pragma unroll
                for (int nt = 0; nt < 4; nt++) {
                    int c = n0 + wx * 32 + nt * 8 + (lane & 3) * 2;
                    int h = c >> 6, dk = c & 63;
                    float v0 = acc[mt][nt][half_ * 2 + 0];
                    float v1 = acc[mt][nt][half_ * 2 + 1];
                    if (z == 2) {
                        size_t base = ((size_t)(b * NHEAD + h) * DK + dk) * SEQ + s;
                        g_Vt[base] = __float2half_rn(v0);
                        g_Vt[base + SEQ] = __float2half_rn(v1);
                    } else {
                        __half* Out = (z == 0) ? g_Qh : g_Kh;
                        *(__half2*)(Out + ((size_t)(b * NHEAD + h) * SEQ + s) * DK + dk) =
                            __floats2half2_rn(v0, v1);
                    }
                }
            }
        }
    } else {
#pragma unroll
        for (int mt = 0; mt < 4; mt++) {
            int rA = m0 + wy * 64 + mt * 16 + (lane >> 2);
#pragma unroll
            for (int half_ = 0; half_ < 2; half_++) {
                int r = rA + half_ * 8;
#pragma unroll
                for (int nt = 0; nt < 4; nt++) {
                    int c = n0 + wx * 32 + nt * 8 + (lane & 3) * 2;
                    float2 bb = *(const float2*)(bias + c);
                    float2 v = make_float2(acc[mt][nt][half_ * 2 + 0] + bb.x,
                                           acc[mt][nt][half_ * 2 + 1] + bb.y);
                    *(float2*)(Cp + (size_t)r * DMODEL + c) = v;
                }
            }
        }
    }
}

// =====================================================================
// Fused attention, cp.async double-buffered 64-key tiles, ldsm4 B-frags.
// =====================================================================
#define LDSK 72
#define KKT 64                       // keys per tile
#define NKT (SEQ / KKT)              // 32 tiles
__global__ __launch_bounds__(256) void fused_attn(const int* __restrict__ mask) {
    __shared__ __align__(16) __half Ks[2 * 64 * LDSK];   // also stages Q (128 rows)
    __shared__ __align__(16) __half Vs[2 * 64 * LDSK];
    __shared__ float Msf[SEQ];

    const int q0 = blockIdx.x * 128;
    const int bh = blockIdx.y;
    const int b = bh >> 4, h = bh & 15;

    const __half* Qg = g_Qh + (size_t)bh * SEQ * DK;
    const __half* Kg = g_Kh + (size_t)bh * SEQ * DK;
    const __half* Vg = g_Vt + (size_t)bh * DK * SEQ;
    __half* P = g_P + (size_t)bh * SEQ * SEQ;

    const int tid = threadIdx.x;
    const int wid = tid >> 5, lane = tid & 31;
    const int g = lane >> 2;       // row group 0..7
    const int t4 = lane & 3;       // col pair selector

    // ---- stage Q (128x64) into Ks region + full mask row ----
#pragma unroll
    for (int i = 0; i < 4; i++) {
        int idx = tid + i * 256;               // 0..1023
        int row = idx >> 3, c8 = (idx & 7) * 8;
        *(uint4*)&Ks[row * LDSK + c8] = *(const uint4*)(Qg + (size_t)(q0 + row) * DK + c8);
    }
#pragma unroll
    for (int i = 0; i < SEQ / 256; i++)
        Msf[i * 256 + tid] = mask[b * SEQ + i * 256 + tid] ? 1.f : 0.f;
    __syncthreads();

    uint32_t aq[4][4];
    {
        int base = (wid * 16 + (lane & 15)) * LDSK + (lane >> 4) * 8;
#pragma unroll
        for (int kc = 0; kc < 4; kc++)
            ldsm4(aq[kc][0], aq[kc][1], aq[kc][2], aq[kc][3], smaddr(&Ks[base + kc * 16]));
    }
    __syncthreads();   // Q fully consumed before Ks reused for K tiles

    float acc_o[8][4];
#pragma unroll
    for (int i = 0; i < 8; i++)
#pragma unroll
        for (int j = 0; j < 4; j++) acc_o[i][j] = 0.f;
    float rs0 = 0.f, rs1 = 0.f;

    // ldsm4 B-frag offsets: nt2 covers n-tiles {2*nt2, 2*nt2+1}
    int koff4[4];
#pragma unroll
    for (int nt2 = 0; nt2 < 4; nt2++)
        koff4[nt2] = (nt2 * 16 + ((lane >> 4) & 1) * 8 + (lane & 7)) * LDSK
                     + ((lane >> 3) & 1) * 8;

    // loader indices: 2 x 16B chunks each for K and V per stage
    const int lrow0 = tid >> 3, lc8 = (tid & 7) * 8;          // rows 0..31
    const int lrow1 = (tid + 256) >> 3;                        // rows 32..63

    // ---- prologue: stage 0 ----
    {
        cp_async16(smaddr(&Ks[lrow0 * LDSK + lc8]), Kg + (size_t)lrow0 * DK + lc8);
        cp_async16(smaddr(&Ks[lrow1 * LDSK + lc8]), Kg + (size_t)lrow1 * DK + lc8);
        cp_async16(smaddr(&Vs[lrow0 * LDSK + lc8]), Vg + (size_t)lrow0 * SEQ + lc8);
        cp_async16(smaddr(&Vs[lrow1 * LDSK + lc8]), Vg + (size_t)lrow1 * SEQ + lc8);
        CP_COMMIT();
    }

#pragma unroll 1
    for (int kt = 0; kt < NKT; kt++) {
        CP_WAIT0();
        __syncthreads();

        if (kt + 1 < NKT) {
            int sb = ((kt + 1) & 1) * 64 * LDSK;
            int kb = (kt + 1) * KKT;
            cp_async16(smaddr(&Ks[sb + lrow0 * LDSK + lc8]),
                       Kg + (size_t)(kb + lrow0) * DK + lc8);
            cp_async16(smaddr(&Ks[sb + lrow1 * LDSK + lc8]),
                       Kg + (size_t)(kb + lrow1) * DK + lc8);
            cp_async16(smaddr(&Vs[sb + lrow0 * LDSK + lc8]),
                       Vg + (size_t)lrow0 * SEQ + kb + lc8);
            cp_async16(smaddr(&Vs[sb + lrow1 * LDSK + lc8]),
                       Vg + (size_t)lrow1 * SEQ + kb + lc8);
            CP_COMMIT();
        }

        const int cb = (kt & 1) * 64 * LDSK;

        // ---- scores: m16 x n64, k=64 (ldsm4 B: 4 loads per kc) ----
        float sc[8][4];
#pragma unroll
        for (int nt = 0; nt < 8; nt++)
#pragma unroll
            for (int j = 0; j < 4; j++) sc[nt][j] = 0.f;
#pragma unroll
        for (int kc = 0; kc < 4; kc++) {
#pragma unroll
            for (int nt2 = 0; nt2 < 4; nt2++) {
                uint32_t b0, b1, b2, b3;
                ldsm4(b0, b1, b2, b3, smaddr(&Ks[cb + koff4[nt2] + kc * 16]));
                mma16816(sc[nt2 * 2 + 0], aq[kc][0], aq[kc][1], aq[kc][2], aq[kc][3], b0, b1);
                mma16816(sc[nt2 * 2 + 1], aq[kc][0], aq[kc][1], aq[kc][2], aq[kc][3], b2, b3);
            }
        }

        // ---- exp*mask, rowsum, store P, build fp16 A-frags ----
        uint32_t ae[4][4];
        int rgl = q0 + wid * 16 + g;
#pragma unroll
        for (int nt = 0; nt < 8; nt++) {
            int cl = nt * 8 + t4 * 2;
            float m0 = Msf[kt * KKT + cl], m1 = Msf[kt * KKT + cl + 1];
            float p0 = __expf(sc[nt][0] * SCALE) * m0;
            float p1 = __expf(sc[nt][1] * SCALE) * m1;
            float p2 = __expf(sc[nt][2] * SCALE) * m0;
            float p3 = __expf(sc[nt][3] * SCALE) * m1;
            rs0 += p0 + p1;
            rs1 += p2 + p3;
            __half2 h01 = __floats2half2_rn(p0, p1);
            __half2 h23 = __floats2half2_rn(p2, p3);
            *(__half2*)(P + (size_t)rgl * SEQ + kt * KKT + cl) = h01;
            *(__half2*)(P + (size_t)(rgl + 8) * SEQ + kt * KKT + cl) = h23;
            ae[nt >> 1][(nt & 1) * 2 + 0] = *(uint32_t*)&h01;
            ae[nt >> 1][(nt & 1) * 2 + 1] = *(uint32_t*)&h23;
        }

        // ---- ctx: acc_o += p @ V  (m16 x n64, k=64; ldsm4 B) ----
#pragma unroll
        for (int kc = 0; kc < 4; kc++) {
#pragma unroll
            for (int nt2 = 0; nt2 < 4; nt2++) {
                uint32_t b0, b1, b2, b3;
                ldsm4(b0, b1, b2, b3, smaddr(&Vs[cb + koff4[nt2] + kc * 16]));
                mma16816(acc_o[nt2 * 2 + 0], ae[kc][0], ae[kc][1], ae[kc][2], ae[kc][3], b0, b1);
                mma16816(acc_o[nt2 * 2 + 1], ae[kc][0], ae[kc][1], ae[kc][2], ae[kc][3], b2, b3);
            }
        }
    }

    // ---- reduce rowsum across quad, write, normalize, store ctx ----
    rs0 += __shfl_xor_sync(0xFFFFFFFFu, rs0, 1);
    rs0 += __shfl_xor_sync(0xFFFFFFFFu, rs0, 2);
    rs1 += __shfl_xor_sync(0xFFFFFFFFu, rs1, 1);
    rs1 += __shfl_xor_sync(0xFFFFFFFFu, rs1, 2);

    int r = q0 + wid * 16 + g;
    if (t4 == 0) {
        g_rowsum[(size_t)bh * SEQ + r] = rs0;
        g_rowsum[(size_t)bh * SEQ + r + 8] = rs1;
    }
    float inv0 = 1.0f / rs0, inv1 = 1.0f / rs1;
#pragma unroll
    for (int nt = 0; nt < 8; nt++) {
        int c = h * DK + nt * 8 + t4 * 2;
        *(__half2*)(g_Ch + ((size_t)(b * SEQ + r)) * DMODEL + c) =
            __floats2half2_rn(acc_o[nt][0] * inv0, acc_o[nt][1] * inv0);
        *(__half2*)(g_Ch + ((size_t)(b * SEQ + r + 8)) * DMODEL + c) =
            __floats2half2_rn(acc_o[nt][2] * inv1, acc_o[nt][3] * inv1);
    }
}

// =====================================================================
// Head-mean of normalized probs — uint4 loads (near DRAM roofline; keep).
// =====================================================================
__global__ __launch_bounds__(256) void mean_kernel(float* __restrict__ out_mean) {
    int q = blockIdx.x;
    int b = blockIdx.y;
    int tid = threadIdx.x;

    float macc[8];
#pragma unroll
    for (int j = 0; j < 8; j++) macc[j] = 0.f;

#pragma unroll 1
    for (int h = 0; h < NHEAD; h++) {
        const uint4* row = (const uint4*)(g_P + (((size_t)(b * NHEAD + h)) * SEQ + q) * SEQ);
        float inv = 1.0f / g_rowsum[(size_t)(b * NHEAD + h) * SEQ + q];
        uint4 raw = row[tid];
        const __half2* hh = (const __half2*)&raw;
#pragma unroll
        for (int j = 0; j < 4; j++) {
            float2 f = __half22float2(hh[j]);
            macc[j * 2 + 0] += f.x * inv;
            macc[j * 2 + 1] += f.y * inv;
        }
    }

    float* om = out_mean + ((size_t)(b * SEQ + q)) * SEQ + tid * 8;
    const float invH = 1.0f / NHEAD;
    float4 o0 = make_float4(macc[0] * invH, macc[1] * invH, macc[2] * invH, macc[3] * invH);
    float4 o1 = make_float4(macc[4] * invH, macc[5] * invH, macc[6] * invH, macc[7] * invH);
    *(float4*)om = o0;
    *(float4*)(om + 4) = o1;
}

// =====================================================================
extern "C" void kernel_launch(void* const* d_in, const int* in_sizes, int n_in,
                              void* d_out, int out_size) {
    const float* query = (const float*)d_in[0];
    const float* key   = (const float*)d_in[1];
    const float* value = (const float*)d_in[2];
    const int*   mask  = (const int*)d_in[3];
    const float* W_q   = (const float*)d_in[4];
    const float* W_k   = (const float*)d_in[5];
    const float* W_v   = (const float*)d_in[6];
    const float* W_o   = (const float*)d_in[7];
    const float* b_o   = (const float*)d_in[8];

    float* out_main = (float*)d_out;                                    // [B,S,D]
    float* out_mean = out_main + (size_t)BATCH * SEQ * DMODEL;          // [B,S,S]

    dim3 blk(256);

    // single fused fp32->fp16 conversion
    const int ntot = 3 * NX4 + 4 * NW4;
    cvt_all<<<ntot / 256, blk>>>(query, key, value, W_q, W_k, W_v, W_o);

    // QKV projections (z = which)
    mgemm<0><<<dim3(DMODEL / 128, (BATCH * SEQ) / 128, 3), blk>>>(nullptr, nullptr);

    // fused scores + exp + rowsum + P store + P@V + normalize (pipelined)
    fused_attn<<<dim3(SEQ / 128, BATCH * NHEAD), blk>>>(mask);

    mean_kernel<<<dim3(SEQ, BATCH), blk>>>(out_mean);

    // output projection
    mgemm<2><<<dim3(DMODEL / 128, (BATCH * SEQ) / 128, 1), blk>>>(b_o, out_main);
}